// round 10
// baseline (speedup 1.0000x reference)
#include <cuda_runtime.h>
#include <math.h>
#include <stdint.h>

#define SCALE 16
#define R_MAX 4
#define HL 32
#define WL 32
#define HH 512
#define WH 512
#define C_FEAT 128
#define HW (HH * WH)

// prep scratch
__device__ float g_guide_lr[3 * HL * WL];
__device__ float g_feat_t[HL * WL * C_FEAT];   // [spatial][channel]

// ---------------- dynamic smem layout (bytes) ----------------
// F slot-major: uint2 {hi, lo} per (slot, channel). Stride 132 uint2
// (132 mod 16 = 4 -> word-stride 264 mod 32 = 8): fragment LDS.64 banks are
// 8*lr + 2*lq + {0,1} (disjoint pairs, distinct within each 16-lane phase),
// build STS.64 banks are 2c (distinct) -> fully conflict-free.
#define SLOT_STRIDE_U2 132
#define NSLOT_MAX   32
#define OFF_SCAL   0            // floats: ct, st, isx, isy, isr, Rsq
#define OFF_NACT   32
#define OFF_SI     64           // int[64]
#define OFF_DXF    320          // float[64]
#define OFF_DYF    576          // float[64]
#define OFF_P0     832          // float4[64]
#define OFF_P1     1856         // float2[64]
#define OFF_F      2432
#define SMEM_BYTES (OFF_F + NSLOT_MAX * SLOT_STRIDE_U2 * 8)   // 36224 B

// pack two floats to bf16x2 (lo 16 bits = w0)
static __device__ __forceinline__ uint32_t pack_bf16x2(float w0, float w1) {
    uint32_t r;
    asm("cvt.rn.bf16x2.f32 %0, %1, %2;" : "=r"(r) : "f"(w1), "f"(w0));
    return r;
}

#define MMA_BF16(d, a0, a1, a2, a3, b0, b1) \
    asm volatile("mma.sync.aligned.m16n8k16.row.col.f32.bf16.bf16.f32 " \
        "{%0,%1,%2,%3}, {%4,%5,%6,%7}, {%8,%9}, {%0,%1,%2,%3};" \
        : "+f"((d)[0]), "+f"((d)[1]), "+f"((d)[2]), "+f"((d)[3]) \
        : "r"(a0), "r"(a1), "r"(a2), "r"(a3), "r"(b0), "r"(b1))

// ---------------------------------------------------------------------------
// Prep: transpose feat to channel-minor; bilinear-downsample guide (separable,
// rows then columns, matching the reference).
// ---------------------------------------------------------------------------
__global__ void jbu_prep_kernel(const float* __restrict__ feat,
                                const float* __restrict__ guide) {
    int idx = blockIdx.x * blockDim.x + threadIdx.x;

    if (idx < HL * WL * C_FEAT) {
        int c = idx & (C_FEAT - 1);
        int s = idx >> 7;
        g_feat_t[idx] = feat[c * (HL * WL) + s];
    }
    if (idx < 3 * HL * WL) {
        int c = idx >> 10;
        int rem = idx & 1023;
        int i = rem >> 5;
        int j = rem & 31;

        float srcy = fmaxf((i + 0.5f) * ((float)HH / HL) - 0.5f, 0.0f);
        int r0 = (int)floorf(srcy);
        float tr = srcy - (float)r0;
        int r0c = min(max(r0, 0), HH - 1);
        int r1c = min(max(r0 + 1, 0), HH - 1);

        float srcx = fmaxf((j + 0.5f) * ((float)WH / WL) - 0.5f, 0.0f);
        int c0 = (int)floorf(srcx);
        float tc = srcx - (float)c0;
        int c0c = min(max(c0, 0), WH - 1);
        int c1c = min(max(c0 + 1, 0), WH - 1);

        const float* g = guide + c * HW;
        float v0 = g[r0c * WH + c0c] * (1.0f - tr) + g[r1c * WH + c0c] * tr;
        float v1 = g[r0c * WH + c1c] * (1.0f - tr) + g[r1c * WH + c1c] * tr;
        g_guide_lr[idx] = v0 * (1.0f - tc) + v1 * tc;
    }
}

// ---------------------------------------------------------------------------
// Main: one block per HALF LR cell (8 HR rows x 16 cols x 128 ch).
// num = W[128xK] * F[Kx128] via mma.sync bf16 m16n8k16, hi/lo split
// (hh + lh + hl). W (A fragments) computed IN REGISTERS by the owning thread,
// interleaved with the MMAs; only F is staged in smem (uint2-packed hi/lo).
// den exact fp32 via quad shfl reduction. 256 threads; warp w owns HR row w.
// ---------------------------------------------------------------------------
__global__ __launch_bounds__(256, 2)
void jbu_main_kernel(const float* __restrict__ guide,
                     const float* __restrict__ sx_raw,
                     const float* __restrict__ sy_raw,
                     const float* __restrict__ th_raw,
                     const float* __restrict__ sr_raw,
                     float* __restrict__ out) {
    extern __shared__ __align__(16) char smem[];

    float*    s_scal = (float*)(smem + OFF_SCAL);
    int*      s_nactp = (int*)(smem + OFF_NACT);
    int*      s_si   = (int*)(smem + OFF_SI);
    float*    s_dxf  = (float*)(smem + OFF_DXF);
    float*    s_dyf  = (float*)(smem + OFF_DYF);
    float4*   s_p0   = (float4*)(smem + OFF_P0);
    float2*   s_p1   = (float2*)(smem + OFF_P1);
    uint2*    Fuv    = (uint2*)(smem + OFF_F);

    const int uc = blockIdx.y;
    const int vc = blockIdx.x;
    const int zh = blockIdx.z;       // 0/1: which 8-row half of the 16x16 tile
    const int tid = threadIdx.x;
    const int wid = tid >> 5;
    const int lane = tid & 31;

    // ---- phase 0: params + offset compaction (warp 0, ballot-based) ----
    if (wid == 0) {
        if (lane == 0) {
            int cell = uc * WL + vc;
            float sx = fmaxf(expf(sx_raw[cell]), 1e-6f);
            float sy = fmaxf(expf(sy_raw[cell]), 1e-6f);
            float th = 3.14159265358979323846f * tanhf(th_raw[cell]);
            float sr = fmaxf(expf(sr_raw[cell]), 1e-6f);
            float rr = fminf(fmaxf(2.0f * fmaxf(sx, sy), 1.0f), (float)R_MAX);
            s_scal[0] = cosf(th);
            s_scal[1] = sinf(th);
            s_scal[2] = 1.0f / (2.0f * sx * sx + 1e-8f);
            s_scal[3] = 1.0f / (2.0f * sy * sy + 1e-8f);
            s_scal[4] = 1.0f / (2.0f * sr * sr + 1e-8f);
            s_scal[5] = rr * rr;
        }
        __syncwarp();
        const float Rsq = s_scal[5];
        int base = 0;
#pragma unroll
        for (int chnk = 0; chnk < 3; chnk++) {
            int i = chnk * 32 + lane;
            int dy = i / 9 - R_MAX;
            int dx = i - (i / 9) * 9 - R_MAX;
            bool act = (i < 81) && ((float)(dy * dy + dx * dx) <= Rsq);
            unsigned m = __ballot_sync(0xffffffffu, act);
            int pos = base + __popc(m & ((1u << lane) - 1u));
            if (act) {
                int ui = min(max(uc + dy, 0), HL - 1);
                int vi = min(max(vc + dx, 0), WL - 1);
                s_dyf[pos] = (float)(uc - ui);
                s_dxf[pos] = (float)(vc - vi);
                s_si[pos]  = ui * WL + vi;
            }
            base += __popc(m);
        }
        if (lane == 0) *s_nactp = base;
    }
    __syncthreads();

    const int nact = *s_nactp;                 // <= 49
    const int ksteps = (nact + 15) >> 4;       // <= 4
    const int nslots = ksteps * 8;             // kpair slots, <= 32
    const float ct  = s_scal[0];
    const float st  = s_scal[1];
    const float isx = s_scal[2];
    const float isy = s_scal[3];
    const float isr = s_scal[4];

    if (tid < nact) {
        int si = s_si[tid];
        float fdx = s_dxf[tid];
        float fdy = s_dyf[tid];
        float gl0 = g_guide_lr[si];
        float gl1 = g_guide_lr[HL * WL + si];
        float gl2 = g_guide_lr[2 * HL * WL + si];
        float A = fdx * ct + fdy * st;
        float B = fdy * ct - fdx * st;
        float D = (gl0 * gl0 + gl1 * gl1 + gl2 * gl2) * isr;
        s_p0[tid] = make_float4(A, B, D, 2.0f * gl0 * isr);
        s_p1[tid] = make_float2(2.0f * gl1 * isr, 2.0f * gl2 * isr);
    }
    __syncthreads();

    // ---- phase 1: build F (all 256 threads; slot-major, coalesced) ----
    {
        const int nent = nslots * C_FEAT;
        for (int e = tid; e < nent; e += 256) {
            int c = e & 127;
            int s = e >> 7;
            int k0 = 2 * s, k1 = 2 * s + 1;
            float f0 = (k0 < nact) ? g_feat_t[s_si[k0] * C_FEAT + c] : 0.0f;
            float f1 = (k1 < nact) ? g_feat_t[s_si[k1] * C_FEAT + c] : 0.0f;
            uint32_t hi = pack_bf16x2(f0, f1);
            float h0f = __uint_as_float(hi << 16);
            float h1f = __uint_as_float(hi & 0xffff0000u);
            uint32_t lo = pack_bf16x2(f0 - h0f, f1 - h1f);
            Fuv[s * SLOT_STRIDE_U2 + c] = make_uint2(hi, lo);
        }
    }

    // ---- per-pixel constants for the two pixels this thread owns ----
    const int lq = lane >> 2;         // 0..7  (groupID)
    const int lr = lane & 3;          // 0..3  (threadID-in-group)
    const int tyc = zh * 8 + wid;     // row within 16x16 cell
    const int y = uc * SCALE + tyc;
    const int x0 = vc * SCALE + lq;   // pixel 0: x=lq; pixel 1: x=lq+8

    const float* gp0 = guide + (size_t)y * WH + x0;
    const float ga0 = gp0[0],     ga1 = gp0[HW],     ga2 = gp0[2 * HW];
    const float gb0 = gp0[8],     gb1 = gp0[HW + 8], gb2 = gp0[2 * HW + 8];

    const float py = ((float)tyc - 7.5f) * (1.0f / SCALE);
    const float px0 = ((float)lq - 7.5f) * (1.0f / SCALE);
    const float px1 = ((float)(lq + 8) - 7.5f) * (1.0f / SCALE);
    const float pa0 = px0 * ct + py * st;
    const float pb0 = py * ct - px0 * st;
    const float pa1 = px1 * ct + py * st;
    const float pb1 = py * ct - px1 * st;
    const float negE0 = -(ga0 * ga0 + ga1 * ga1 + ga2 * ga2) * isr;
    const float negE1 = -(gb0 * gb0 + gb1 * gb1 + gb2 * gb2) * isr;
    const float nisx = -isx, nisy = -isy;

    float acc[16][4];
#pragma unroll
    for (int nt = 0; nt < 16; nt++)
#pragma unroll
        for (int q = 0; q < 4; q++) acc[nt][q] = 0.0f;
    float den0 = 0.0f, den1 = 0.0f;

    __syncthreads();   // F ready

    // ---- phase 2: fused W-eval + MMA ----
    for (int ks = 0; ks < ksteps; ks++) {
        // Evaluate 8 weights: jp = (pairsel<<1)|khalf gives k; both pixels per k.
        float w[4][2];
#pragma unroll
        for (int jp = 0; jp < 4; jp++) {
            int k = 2 * (ks * 8 + lr + ((jp >> 1) << 2)) + (jp & 1);
            float v0 = 0.0f, v1 = 0.0f;
            if (k < nact) {
                float4 q0 = s_p0[k];
                float2 q1 = s_p1[k];
                float a0 = pa0 + q0.x, b0 = pb0 + q0.y;
                float t0 = negE0 - q0.z;
                t0 = fmaf(ga0, q0.w, t0);
                t0 = fmaf(ga1, q1.x, t0);
                t0 = fmaf(ga2, q1.y, t0);
                t0 = fmaf(a0 * a0, nisx, t0);
                t0 = fmaf(b0 * b0, nisy, t0);
                v0 = __expf(t0);
                float a1 = pa1 + q0.x, b1 = pb1 + q0.y;
                float t1 = negE1 - q0.z;
                t1 = fmaf(gb0, q0.w, t1);
                t1 = fmaf(gb1, q1.x, t1);
                t1 = fmaf(gb2, q1.y, t1);
                t1 = fmaf(a1 * a1, nisx, t1);
                t1 = fmaf(b1 * b1, nisy, t1);
                v1 = __expf(t1);
            }
            w[jp][0] = v0;
            w[jp][1] = v1;
        }
        den0 += w[0][0] + w[1][0] + w[2][0] + w[3][0];
        den1 += w[0][1] + w[1][1] + w[2][1] + w[3][1];

        // A fragments (hi + residual-lo)
        uint32_t ah0 = pack_bf16x2(w[0][0], w[1][0]);
        uint32_t ah1 = pack_bf16x2(w[0][1], w[1][1]);
        uint32_t ah2 = pack_bf16x2(w[2][0], w[3][0]);
        uint32_t ah3 = pack_bf16x2(w[2][1], w[3][1]);
        uint32_t al0 = pack_bf16x2(w[0][0] - __uint_as_float(ah0 << 16),
                                   w[1][0] - __uint_as_float(ah0 & 0xffff0000u));
        uint32_t al1 = pack_bf16x2(w[0][1] - __uint_as_float(ah1 << 16),
                                   w[1][1] - __uint_as_float(ah1 & 0xffff0000u));
        uint32_t al2 = pack_bf16x2(w[2][0] - __uint_as_float(ah2 << 16),
                                   w[3][0] - __uint_as_float(ah2 & 0xffff0000u));
        uint32_t al3 = pack_bf16x2(w[2][1] - __uint_as_float(ah3 << 16),
                                   w[3][1] - __uint_as_float(ah3 & 0xffff0000u));

        const int sA = (ks * 8 + lr) * SLOT_STRIDE_U2;        // kpair lr
        const int sB = (ks * 8 + lr + 4) * SLOT_STRIDE_U2;    // kpair lr+4
#pragma unroll
        for (int nt = 0; nt < 16; nt++) {
            const int cb = nt * 8 + lq;
            uint2 B0 = Fuv[sA + cb];   // {bh0, bl0}
            uint2 B1 = Fuv[sB + cb];   // {bh1, bl1}
            MMA_BF16(acc[nt], ah0, ah1, ah2, ah3, B0.x, B1.x);
            MMA_BF16(acc[nt], al0, al1, al2, al3, B0.x, B1.x);
            MMA_BF16(acc[nt], ah0, ah1, ah2, ah3, B0.y, B1.y);
        }
    }

    // ---- phase 3: den quad-reduction + epilogue ----
    den0 += __shfl_xor_sync(0xffffffffu, den0, 1);
    den0 += __shfl_xor_sync(0xffffffffu, den0, 2);
    den1 += __shfl_xor_sync(0xffffffffu, den1, 1);
    den1 += __shfl_xor_sync(0xffffffffu, den1, 2);
    const float inv0 = 1.0f / fmaxf(den0, 1e-8f);
    const float inv1 = 1.0f / fmaxf(den1, 1e-8f);

    float* obase = out + (size_t)y * WH + x0;
#pragma unroll
    for (int nt = 0; nt < 16; nt++) {
        const int ch = nt * 8 + lr * 2;
        float* o = obase + (size_t)ch * HW;
        o[0]      = acc[nt][0] * inv0;
        o[HW]     = acc[nt][1] * inv0;
        o[8]      = acc[nt][2] * inv1;
        o[HW + 8] = acc[nt][3] * inv1;
    }
}

extern "C" void kernel_launch(void* const* d_in, const int* in_sizes, int n_in,
                              void* d_out, int out_size) {
    const float* feat  = (const float*)d_in[0];
    const float* guide = (const float*)d_in[1];
    const float* sx    = (const float*)d_in[2];
    const float* sy    = (const float*)d_in[3];
    const float* th    = (const float*)d_in[4];
    const float* sr    = (const float*)d_in[5];
    float* out = (float*)d_out;

    cudaFuncSetAttribute(jbu_main_kernel,
                         cudaFuncAttributeMaxDynamicSharedMemorySize, SMEM_BYTES);

    jbu_prep_kernel<<<512, 256>>>(feat, guide);
    dim3 grid(WL, HL, 2);
    jbu_main_kernel<<<grid, 256, SMEM_BYTES>>>(guide, sx, sy, th, sr, out);
}

// round 11
// speedup vs baseline: 1.2244x; 1.2244x over previous
#include <cuda_runtime.h>
#include <math.h>
#include <stdint.h>

#define SCALE 16
#define R_MAX 4
#define HL 32
#define WL 32
#define HH 512
#define WH 512
#define C_FEAT 128
#define HW (HH * WH)

// prep scratch
__device__ float g_guide_lr[3 * HL * WL];
__device__ float g_feat_t[HL * WL * C_FEAT];   // [spatial][channel]

// ---------------- dynamic smem layout (bytes) ----------------
// F slot-major: array[slot][channel], stride 136 words (136 mod 32 = 8).
// Fragment loads: bank = 8*lr + lq -> bijection, conflict-free.
#define SLOT_STRIDE 136
#define NSLOT_MAX   32
#define OFF_SCAL   0            // floats: ct, st, isx, isy, isr, Rsq
#define OFF_NACT   32
#define OFF_SI     64           // int[64]
#define OFF_DXF    320          // float[64]
#define OFF_DYF    576          // float[64]
#define OFF_P0     832          // float4[64]
#define OFF_P1     1856         // float2[64]
#define OFF_FHI    2432
#define OFF_FLO    (OFF_FHI + NSLOT_MAX * SLOT_STRIDE * 4)
#define SMEM_BYTES (OFF_FLO + NSLOT_MAX * SLOT_STRIDE * 4)   // 37248 B

// pack two floats to bf16x2 (lo 16 bits = w0)
static __device__ __forceinline__ uint32_t pack_bf16x2(float w0, float w1) {
    uint32_t r;
    asm("cvt.rn.bf16x2.f32 %0, %1, %2;" : "=r"(r) : "f"(w1), "f"(w0));
    return r;
}

#define MMA_BF16(d, a0, a1, a2, a3, b0, b1) \
    asm volatile("mma.sync.aligned.m16n8k16.row.col.f32.bf16.bf16.f32 " \
        "{%0,%1,%2,%3}, {%4,%5,%6,%7}, {%8,%9}, {%0,%1,%2,%3};" \
        : "+f"((d)[0]), "+f"((d)[1]), "+f"((d)[2]), "+f"((d)[3]) \
        : "r"(a0), "r"(a1), "r"(a2), "r"(a3), "r"(b0), "r"(b1))

// ---------------------------------------------------------------------------
// Prep: transpose feat to channel-minor; bilinear-downsample guide (separable,
// rows then columns, matching the reference).
// ---------------------------------------------------------------------------
__global__ void jbu_prep_kernel(const float* __restrict__ feat,
                                const float* __restrict__ guide) {
    int idx = blockIdx.x * blockDim.x + threadIdx.x;

    if (idx < HL * WL * C_FEAT) {
        int c = idx & (C_FEAT - 1);
        int s = idx >> 7;
        g_feat_t[idx] = feat[c * (HL * WL) + s];
    }
    if (idx < 3 * HL * WL) {
        int c = idx >> 10;
        int rem = idx & 1023;
        int i = rem >> 5;
        int j = rem & 31;

        float srcy = fmaxf((i + 0.5f) * ((float)HH / HL) - 0.5f, 0.0f);
        int r0 = (int)floorf(srcy);
        float tr = srcy - (float)r0;
        int r0c = min(max(r0, 0), HH - 1);
        int r1c = min(max(r0 + 1, 0), HH - 1);

        float srcx = fmaxf((j + 0.5f) * ((float)WH / WL) - 0.5f, 0.0f);
        int c0 = (int)floorf(srcx);
        float tc = srcx - (float)c0;
        int c0c = min(max(c0, 0), WH - 1);
        int c1c = min(max(c0 + 1, 0), WH - 1);

        const float* g = guide + c * HW;
        float v0 = g[r0c * WH + c0c] * (1.0f - tr) + g[r1c * WH + c0c] * tr;
        float v1 = g[r0c * WH + c1c] * (1.0f - tr) + g[r1c * WH + c1c] * tr;
        g_guide_lr[idx] = v0 * (1.0f - tc) + v1 * tc;
    }
}

// ---------------------------------------------------------------------------
// Main: one block per HALF LR cell (8 HR rows x 16 cols x 128 ch).
// Restructured for occupancy: W fragments for ALL k-steps are computed first
// into 32 registers, den finalized, THEN channel pairs are streamed with
// transient accumulators (8 regs) and immediate stores. 3 blocks/SM.
// ---------------------------------------------------------------------------
__global__ __launch_bounds__(256, 3)
void jbu_main_kernel(const float* __restrict__ guide,
                     const float* __restrict__ sx_raw,
                     const float* __restrict__ sy_raw,
                     const float* __restrict__ th_raw,
                     const float* __restrict__ sr_raw,
                     float* __restrict__ out) {
    extern __shared__ __align__(16) char smem[];

    float*    s_scal = (float*)(smem + OFF_SCAL);
    int*      s_nactp = (int*)(smem + OFF_NACT);
    int*      s_si   = (int*)(smem + OFF_SI);
    float*    s_dxf  = (float*)(smem + OFF_DXF);
    float*    s_dyf  = (float*)(smem + OFF_DYF);
    float4*   s_p0   = (float4*)(smem + OFF_P0);
    float2*   s_p1   = (float2*)(smem + OFF_P1);
    uint32_t* Fhi    = (uint32_t*)(smem + OFF_FHI);
    uint32_t* Flo    = (uint32_t*)(smem + OFF_FLO);

    const int uc = blockIdx.y;
    const int vc = blockIdx.x;
    const int zh = blockIdx.z;       // 0/1: which 8-row half of the 16x16 tile
    const int tid = threadIdx.x;
    const int wid = tid >> 5;
    const int lane = tid & 31;

    // ---- phase 0: params + offset compaction (warp 0, ballot-based) ----
    if (wid == 0) {
        if (lane == 0) {
            int cell = uc * WL + vc;
            float sx = fmaxf(expf(sx_raw[cell]), 1e-6f);
            float sy = fmaxf(expf(sy_raw[cell]), 1e-6f);
            float th = 3.14159265358979323846f * tanhf(th_raw[cell]);
            float sr = fmaxf(expf(sr_raw[cell]), 1e-6f);
            float rr = fminf(fmaxf(2.0f * fmaxf(sx, sy), 1.0f), (float)R_MAX);
            s_scal[0] = cosf(th);
            s_scal[1] = sinf(th);
            s_scal[2] = 1.0f / (2.0f * sx * sx + 1e-8f);
            s_scal[3] = 1.0f / (2.0f * sy * sy + 1e-8f);
            s_scal[4] = 1.0f / (2.0f * sr * sr + 1e-8f);
            s_scal[5] = rr * rr;
        }
        __syncwarp();
        const float Rsq = s_scal[5];
        int base = 0;
#pragma unroll
        for (int chnk = 0; chnk < 3; chnk++) {
            int i = chnk * 32 + lane;
            int dy = i / 9 - R_MAX;
            int dx = i - (i / 9) * 9 - R_MAX;
            bool act = (i < 81) && ((float)(dy * dy + dx * dx) <= Rsq);
            unsigned m = __ballot_sync(0xffffffffu, act);
            int pos = base + __popc(m & ((1u << lane) - 1u));
            if (act) {
                int ui = min(max(uc + dy, 0), HL - 1);
                int vi = min(max(vc + dx, 0), WL - 1);
                s_dyf[pos] = (float)(uc - ui);
                s_dxf[pos] = (float)(vc - vi);
                s_si[pos]  = ui * WL + vi;
            }
            base += __popc(m);
        }
        if (lane == 0) *s_nactp = base;
    }
    __syncthreads();

    const int nact = *s_nactp;                 // <= 49
    const int ksteps = (nact + 15) >> 4;       // <= 4
    const int nslots = ksteps * 8;             // kpair slots, <= 32
    const float ct  = s_scal[0];
    const float st  = s_scal[1];
    const float isx = s_scal[2];
    const float isy = s_scal[3];
    const float isr = s_scal[4];

    if (tid < nact) {
        int si = s_si[tid];
        float fdx = s_dxf[tid];
        float fdy = s_dyf[tid];
        float gl0 = g_guide_lr[si];
        float gl1 = g_guide_lr[HL * WL + si];
        float gl2 = g_guide_lr[2 * HL * WL + si];
        float A = fdx * ct + fdy * st;
        float B = fdy * ct - fdx * st;
        float D = (gl0 * gl0 + gl1 * gl1 + gl2 * gl2) * isr;
        s_p0[tid] = make_float4(A, B, D, 2.0f * gl0 * isr);
        s_p1[tid] = make_float2(2.0f * gl1 * isr, 2.0f * gl2 * isr);
    }
    __syncthreads();

    // ---- phase 1: build F (all 256 threads; slot-major, coalesced) ----
    {
        const int nent = nslots * C_FEAT;
        for (int e = tid; e < nent; e += 256) {
            int c = e & 127;
            int s = e >> 7;
            int k0 = 2 * s, k1 = 2 * s + 1;
            float f0 = (k0 < nact) ? g_feat_t[s_si[k0] * C_FEAT + c] : 0.0f;
            float f1 = (k1 < nact) ? g_feat_t[s_si[k1] * C_FEAT + c] : 0.0f;
            uint32_t hi = pack_bf16x2(f0, f1);
            float h0f = __uint_as_float(hi << 16);
            float h1f = __uint_as_float(hi & 0xffff0000u);
            uint32_t lo = pack_bf16x2(f0 - h0f, f1 - h1f);
            Fhi[s * SLOT_STRIDE + c] = hi;
            Flo[s * SLOT_STRIDE + c] = lo;
        }
    }

    const int lq = lane >> 2;         // 0..7  (groupID)
    const int lr = lane & 3;          // 0..3  (threadID-in-group)
    const int tyc = zh * 8 + wid;     // row within 16x16 cell
    const int y = uc * SCALE + tyc;
    const int x0 = vc * SCALE + lq;   // pixel 0: x=lq; pixel 1: x=lq+8

    // ---- phase 2a: W fragments for ALL k-steps into registers ----
    uint32_t ah[4][4], al[4][4];
    float den0 = 0.0f, den1 = 0.0f;
    {
        const float* gp0 = guide + (size_t)y * WH + x0;
        const float ga0 = gp0[0],     ga1 = gp0[HW],     ga2 = gp0[2 * HW];
        const float gb0 = gp0[8],     gb1 = gp0[HW + 8], gb2 = gp0[2 * HW + 8];

        const float py = ((float)tyc - 7.5f) * (1.0f / SCALE);
        const float px0 = ((float)lq - 7.5f) * (1.0f / SCALE);
        const float px1 = ((float)(lq + 8) - 7.5f) * (1.0f / SCALE);
        const float pa0 = px0 * ct + py * st;
        const float pb0 = py * ct - px0 * st;
        const float pa1 = px1 * ct + py * st;
        const float pb1 = py * ct - px1 * st;
        const float negE0 = -(ga0 * ga0 + ga1 * ga1 + ga2 * ga2) * isr;
        const float negE1 = -(gb0 * gb0 + gb1 * gb1 + gb2 * gb2) * isr;
        const float nisx = -isx, nisy = -isy;

#pragma unroll
        for (int ks = 0; ks < 4; ks++) {
            if (ks >= ksteps) {
#pragma unroll
                for (int j = 0; j < 4; j++) { ah[ks][j] = 0u; al[ks][j] = 0u; }
                continue;
            }
            float w[4][2];
#pragma unroll
            for (int jp = 0; jp < 4; jp++) {
                int k = 2 * (ks * 8 + lr + ((jp >> 1) << 2)) + (jp & 1);
                float v0 = 0.0f, v1 = 0.0f;
                if (k < nact) {
                    float4 q0 = s_p0[k];
                    float2 q1 = s_p1[k];
                    float a0 = pa0 + q0.x, b0 = pb0 + q0.y;
                    float t0 = negE0 - q0.z;
                    t0 = fmaf(ga0, q0.w, t0);
                    t0 = fmaf(ga1, q1.x, t0);
                    t0 = fmaf(ga2, q1.y, t0);
                    t0 = fmaf(a0 * a0, nisx, t0);
                    t0 = fmaf(b0 * b0, nisy, t0);
                    v0 = __expf(t0);
                    float a1 = pa1 + q0.x, b1 = pb1 + q0.y;
                    float t1 = negE1 - q0.z;
                    t1 = fmaf(gb0, q0.w, t1);
                    t1 = fmaf(gb1, q1.x, t1);
                    t1 = fmaf(gb2, q1.y, t1);
                    t1 = fmaf(a1 * a1, nisx, t1);
                    t1 = fmaf(b1 * b1, nisy, t1);
                    v1 = __expf(t1);
                }
                w[jp][0] = v0;
                w[jp][1] = v1;
            }
            den0 += w[0][0] + w[1][0] + w[2][0] + w[3][0];
            den1 += w[0][1] + w[1][1] + w[2][1] + w[3][1];

            uint32_t h0 = pack_bf16x2(w[0][0], w[1][0]);
            uint32_t h1 = pack_bf16x2(w[0][1], w[1][1]);
            uint32_t h2 = pack_bf16x2(w[2][0], w[3][0]);
            uint32_t h3 = pack_bf16x2(w[2][1], w[3][1]);
            ah[ks][0] = h0; ah[ks][1] = h1; ah[ks][2] = h2; ah[ks][3] = h3;
            al[ks][0] = pack_bf16x2(w[0][0] - __uint_as_float(h0 << 16),
                                    w[1][0] - __uint_as_float(h0 & 0xffff0000u));
            al[ks][1] = pack_bf16x2(w[0][1] - __uint_as_float(h1 << 16),
                                    w[1][1] - __uint_as_float(h1 & 0xffff0000u));
            al[ks][2] = pack_bf16x2(w[2][0] - __uint_as_float(h2 << 16),
                                    w[3][0] - __uint_as_float(h2 & 0xffff0000u));
            al[ks][3] = pack_bf16x2(w[2][1] - __uint_as_float(h3 << 16),
                                    w[3][1] - __uint_as_float(h3 & 0xffff0000u));
        }
    }

    // den quad-reduction
    den0 += __shfl_xor_sync(0xffffffffu, den0, 1);
    den0 += __shfl_xor_sync(0xffffffffu, den0, 2);
    den1 += __shfl_xor_sync(0xffffffffu, den1, 1);
    den1 += __shfl_xor_sync(0xffffffffu, den1, 2);
    const float inv0 = 1.0f / fmaxf(den0, 1e-8f);
    const float inv1 = 1.0f / fmaxf(den1, 1e-8f);

    __syncthreads();   // F ready (also ensures phase-1 writes visible)

    // ---- phase 2b: stream channel pairs with transient accumulators ----
    float* obase = out + (size_t)y * WH + x0;
#pragma unroll
    for (int ng = 0; ng < 8; ng++) {
        float acc[2][4];
#pragma unroll
        for (int h = 0; h < 2; h++)
#pragma unroll
            for (int q = 0; q < 4; q++) acc[h][q] = 0.0f;

#pragma unroll
        for (int ks = 0; ks < 4; ks++) {
            if (ks >= ksteps) break;
            const int sA = (ks * 8 + lr) * SLOT_STRIDE;        // kpair lr
            const int sB = (ks * 8 + lr + 4) * SLOT_STRIDE;    // kpair lr+4
#pragma unroll
            for (int h = 0; h < 2; h++) {
                const int cb = (2 * ng + h) * 8 + lq;
                uint32_t bh0 = Fhi[sA + cb];
                uint32_t bh1 = Fhi[sB + cb];
                uint32_t bl0 = Flo[sA + cb];
                uint32_t bl1 = Flo[sB + cb];
                MMA_BF16(acc[h], ah[ks][0], ah[ks][1], ah[ks][2], ah[ks][3], bh0, bh1);
                MMA_BF16(acc[h], al[ks][0], al[ks][1], al[ks][2], al[ks][3], bh0, bh1);
                MMA_BF16(acc[h], ah[ks][0], ah[ks][1], ah[ks][2], ah[ks][3], bl0, bl1);
            }
        }

#pragma unroll
        for (int h = 0; h < 2; h++) {
            const int ch = (2 * ng + h) * 8 + lr * 2;
            float* o = obase + (size_t)ch * HW;
            o[0]      = acc[h][0] * inv0;
            o[HW]     = acc[h][1] * inv0;
            o[8]      = acc[h][2] * inv1;
            o[HW + 8] = acc[h][3] * inv1;
        }
    }
}

extern "C" void kernel_launch(void* const* d_in, const int* in_sizes, int n_in,
                              void* d_out, int out_size) {
    const float* feat  = (const float*)d_in[0];
    const float* guide = (const float*)d_in[1];
    const float* sx    = (const float*)d_in[2];
    const float* sy    = (const float*)d_in[3];
    const float* th    = (const float*)d_in[4];
    const float* sr    = (const float*)d_in[5];
    float* out = (float*)d_out;

    cudaFuncSetAttribute(jbu_main_kernel,
                         cudaFuncAttributeMaxDynamicSharedMemorySize, SMEM_BYTES);

    jbu_prep_kernel<<<512, 256>>>(feat, guide);
    dim3 grid(WL, HL, 2);
    jbu_main_kernel<<<grid, 256, SMEM_BYTES>>>(guide, sx, sy, th, sr, out);
}

// round 12
// speedup vs baseline: 1.3357x; 1.0909x over previous
#include <cuda_runtime.h>
#include <math.h>
#include <stdint.h>

#define SCALE 16
#define R_MAX 4
#define HL 32
#define WL 32
#define HH 512
#define WH 512
#define C_FEAT 128
#define HW (HH * WH)

// prep scratch
__device__ float g_guide_lr[3 * HL * WL];
__device__ float g_feat_t[HL * WL * C_FEAT];   // [spatial][channel]

// ---------------- dynamic smem layout (bytes) ----------------
// F packed as uint4 {hi@kpair q, hi@kpair q+4, lo@q, lo@q+4} indexed
// [ks*4+lr][channel], stride 130 uint4 (130 mod 8 = 2): each LDS.128
// quarter-warp phase (lq 0..1 x lr 0..3) hits u4-index mod 8 = 2*lr+lq,
// all distinct -> 32-bank cover, conflict-free. STS.128 by consecutive c
// likewise conflict-free.
#define CSTR4 130
#define OFF_SCAL   0            // floats: ct, st, isx, isy, isr, Rsq
#define OFF_NACT   32
#define OFF_SI     64           // int[64]
#define OFF_DXF    320          // float[64]
#define OFF_DYF    576          // float[64]
#define OFF_P0     832          // float4[64]
#define OFF_P1     1856         // float2[64]
#define OFF_F4     2432         // uint4[16][CSTR4]
#define SMEM_BYTES (OFF_F4 + 16 * CSTR4 * 16)   // 35712 B

// pack two floats to bf16x2 (lo 16 bits = w0)
static __device__ __forceinline__ uint32_t pack_bf16x2(float w0, float w1) {
    uint32_t r;
    asm("cvt.rn.bf16x2.f32 %0, %1, %2;" : "=r"(r) : "f"(w1), "f"(w0));
    return r;
}

#define MMA_BF16(d, a0, a1, a2, a3, b0, b1) \
    asm volatile("mma.sync.aligned.m16n8k16.row.col.f32.bf16.bf16.f32 " \
        "{%0,%1,%2,%3}, {%4,%5,%6,%7}, {%8,%9}, {%0,%1,%2,%3};" \
        : "+f"((d)[0]), "+f"((d)[1]), "+f"((d)[2]), "+f"((d)[3]) \
        : "r"(a0), "r"(a1), "r"(a2), "r"(a3), "r"(b0), "r"(b1))

// ---------------------------------------------------------------------------
// Prep: transpose feat to channel-minor; bilinear-downsample guide (separable,
// rows then columns, matching the reference).
// ---------------------------------------------------------------------------
__global__ void jbu_prep_kernel(const float* __restrict__ feat,
                                const float* __restrict__ guide) {
    int idx = blockIdx.x * blockDim.x + threadIdx.x;

    if (idx < HL * WL * C_FEAT) {
        int c = idx & (C_FEAT - 1);
        int s = idx >> 7;
        g_feat_t[idx] = feat[c * (HL * WL) + s];
    }
    if (idx < 3 * HL * WL) {
        int c = idx >> 10;
        int rem = idx & 1023;
        int i = rem >> 5;
        int j = rem & 31;

        float srcy = fmaxf((i + 0.5f) * ((float)HH / HL) - 0.5f, 0.0f);
        int r0 = (int)floorf(srcy);
        float tr = srcy - (float)r0;
        int r0c = min(max(r0, 0), HH - 1);
        int r1c = min(max(r0 + 1, 0), HH - 1);

        float srcx = fmaxf((j + 0.5f) * ((float)WH / WL) - 0.5f, 0.0f);
        int c0 = (int)floorf(srcx);
        float tc = srcx - (float)c0;
        int c0c = min(max(c0, 0), WH - 1);
        int c1c = min(max(c0 + 1, 0), WH - 1);

        const float* g = guide + c * HW;
        float v0 = g[r0c * WH + c0c] * (1.0f - tr) + g[r1c * WH + c0c] * tr;
        float v1 = g[r0c * WH + c1c] * (1.0f - tr) + g[r1c * WH + c1c] * tr;
        g_guide_lr[idx] = v0 * (1.0f - tc) + v1 * tc;
    }
}

// ---------------------------------------------------------------------------
// Main: one block per HALF LR cell (8 HR rows x 16 cols x 128 ch).
// 128 threads, 4 warps; warp w owns HR rows 2w and 2w+1 (2 m-tiles) so every
// B fragment (one LDS.128) feeds 6 MMAs. W fragments for all k-steps and both
// m-tiles computed in registers first; channels streamed with transient accs.
// ---------------------------------------------------------------------------
__global__ __launch_bounds__(128, 5)
void jbu_main_kernel(const float* __restrict__ guide,
                     const float* __restrict__ sx_raw,
                     const float* __restrict__ sy_raw,
                     const float* __restrict__ th_raw,
                     const float* __restrict__ sr_raw,
                     float* __restrict__ out) {
    extern __shared__ __align__(16) char smem[];

    float*    s_scal = (float*)(smem + OFF_SCAL);
    int*      s_nactp = (int*)(smem + OFF_NACT);
    int*      s_si   = (int*)(smem + OFF_SI);
    float*    s_dxf  = (float*)(smem + OFF_DXF);
    float*    s_dyf  = (float*)(smem + OFF_DYF);
    float4*   s_p0   = (float4*)(smem + OFF_P0);
    float2*   s_p1   = (float2*)(smem + OFF_P1);
    uint4*    F4     = (uint4*)(smem + OFF_F4);

    const int uc = blockIdx.y;
    const int vc = blockIdx.x;
    const int zh = blockIdx.z;       // 0/1: which 8-row half of the 16x16 tile
    const int tid = threadIdx.x;
    const int wid = tid >> 5;        // 0..3
    const int lane = tid & 31;

    // ---- phase 0: params + offset compaction (warp 0, ballot-based) ----
    if (wid == 0) {
        if (lane == 0) {
            int cell = uc * WL + vc;
            float sx = fmaxf(expf(sx_raw[cell]), 1e-6f);
            float sy = fmaxf(expf(sy_raw[cell]), 1e-6f);
            float th = 3.14159265358979323846f * tanhf(th_raw[cell]);
            float sr = fmaxf(expf(sr_raw[cell]), 1e-6f);
            float rr = fminf(fmaxf(2.0f * fmaxf(sx, sy), 1.0f), (float)R_MAX);
            s_scal[0] = cosf(th);
            s_scal[1] = sinf(th);
            s_scal[2] = 1.0f / (2.0f * sx * sx + 1e-8f);
            s_scal[3] = 1.0f / (2.0f * sy * sy + 1e-8f);
            s_scal[4] = 1.0f / (2.0f * sr * sr + 1e-8f);
            s_scal[5] = rr * rr;
        }
        __syncwarp();
        const float Rsq = s_scal[5];
        int base = 0;
#pragma unroll
        for (int chnk = 0; chnk < 3; chnk++) {
            int i = chnk * 32 + lane;
            int dy = i / 9 - R_MAX;
            int dx = i - (i / 9) * 9 - R_MAX;
            bool act = (i < 81) && ((float)(dy * dy + dx * dx) <= Rsq);
            unsigned m = __ballot_sync(0xffffffffu, act);
            int pos = base + __popc(m & ((1u << lane) - 1u));
            if (act) {
                int ui = min(max(uc + dy, 0), HL - 1);
                int vi = min(max(vc + dx, 0), WL - 1);
                s_dyf[pos] = (float)(uc - ui);
                s_dxf[pos] = (float)(vc - vi);
                s_si[pos]  = ui * WL + vi;
            }
            base += __popc(m);
        }
        if (lane == 0) *s_nactp = base;
    }
    __syncthreads();

    const int nact = *s_nactp;                 // <= 49
    const int ksteps = (nact + 15) >> 4;       // <= 4
    const float ct  = s_scal[0];
    const float st  = s_scal[1];
    const float isx = s_scal[2];
    const float isy = s_scal[3];
    const float isr = s_scal[4];

    if (tid < nact) {
        int si = s_si[tid];
        float fdx = s_dxf[tid];
        float fdy = s_dyf[tid];
        float gl0 = g_guide_lr[si];
        float gl1 = g_guide_lr[HL * WL + si];
        float gl2 = g_guide_lr[2 * HL * WL + si];
        float A = fdx * ct + fdy * st;
        float B = fdy * ct - fdx * st;
        float D = (gl0 * gl0 + gl1 * gl1 + gl2 * gl2) * isr;
        s_p0[tid] = make_float4(A, B, D, 2.0f * gl0 * isr);
        s_p1[tid] = make_float2(2.0f * gl1 * isr, 2.0f * gl2 * isr);
    }
    __syncthreads();

    // ---- phase 1: build F4 (all 128 threads; consecutive c -> conflict-free) ----
    {
        const int nent = ksteps * 4 * C_FEAT;
        for (int e = tid; e < nent; e += 128) {
            int c = e & 127;
            int q = e >> 7;                // ks*4 + lr_b
            int kp0 = (q >> 2) * 8 + (q & 3);
            int kp1 = kp0 + 4;
            int k00 = 2 * kp0, k01 = k00 + 1;
            int k10 = 2 * kp1, k11 = k10 + 1;
            float f00 = (k00 < nact) ? g_feat_t[s_si[k00] * C_FEAT + c] : 0.0f;
            float f01 = (k01 < nact) ? g_feat_t[s_si[k01] * C_FEAT + c] : 0.0f;
            float f10 = (k10 < nact) ? g_feat_t[s_si[k10] * C_FEAT + c] : 0.0f;
            float f11 = (k11 < nact) ? g_feat_t[s_si[k11] * C_FEAT + c] : 0.0f;
            uint32_t hi0 = pack_bf16x2(f00, f01);
            uint32_t hi1 = pack_bf16x2(f10, f11);
            uint32_t lo0 = pack_bf16x2(f00 - __uint_as_float(hi0 << 16),
                                       f01 - __uint_as_float(hi0 & 0xffff0000u));
            uint32_t lo1 = pack_bf16x2(f10 - __uint_as_float(hi1 << 16),
                                       f11 - __uint_as_float(hi1 & 0xffff0000u));
            F4[q * CSTR4 + c] = make_uint4(hi0, hi1, lo0, lo1);
        }
    }

    const int lq = lane >> 2;         // 0..7  (groupID)
    const int lr = lane & 3;          // 0..3  (threadID-in-group)
    const int x0 = vc * SCALE + lq;   // pixel 0: x=lq; pixel 1: x=lq+8

    // ---- phase 2a: W fragments for all k-steps, BOTH m-tiles, into regs ----
    uint32_t ah[2][4][4], al[2][4][4];
    float inv[2][2];
    const float nisx = -isx, nisy = -isy;
    const float px0 = ((float)lq - 7.5f) * (1.0f / SCALE);
    const float px1 = ((float)(lq + 8) - 7.5f) * (1.0f / SCALE);

#pragma unroll
    for (int mt = 0; mt < 2; mt++) {
        const int tyc = zh * 8 + 2 * wid + mt;
        const int y = uc * SCALE + tyc;
        const float* gp0 = guide + (size_t)y * WH + x0;
        const float ga0 = gp0[0],     ga1 = gp0[HW],     ga2 = gp0[2 * HW];
        const float gb0 = gp0[8],     gb1 = gp0[HW + 8], gb2 = gp0[2 * HW + 8];
        const float py = ((float)tyc - 7.5f) * (1.0f / SCALE);
        const float pa0 = px0 * ct + py * st;
        const float pb0 = py * ct - px0 * st;
        const float pa1 = px1 * ct + py * st;
        const float pb1 = py * ct - px1 * st;
        const float negE0 = -(ga0 * ga0 + ga1 * ga1 + ga2 * ga2) * isr;
        const float negE1 = -(gb0 * gb0 + gb1 * gb1 + gb2 * gb2) * isr;

        float den0 = 0.0f, den1 = 0.0f;
#pragma unroll
        for (int ks = 0; ks < 4; ks++) {
            if (ks >= ksteps) {
#pragma unroll
                for (int j = 0; j < 4; j++) { ah[mt][ks][j] = 0u; al[mt][ks][j] = 0u; }
                continue;
            }
            float w[4][2];
#pragma unroll
            for (int jp = 0; jp < 4; jp++) {
                int k = 2 * (ks * 8 + lr + ((jp >> 1) << 2)) + (jp & 1);
                float v0 = 0.0f, v1 = 0.0f;
                if (k < nact) {
                    float4 q0 = s_p0[k];
                    float2 q1 = s_p1[k];
                    float a0 = pa0 + q0.x, b0 = pb0 + q0.y;
                    float t0 = negE0 - q0.z;
                    t0 = fmaf(ga0, q0.w, t0);
                    t0 = fmaf(ga1, q1.x, t0);
                    t0 = fmaf(ga2, q1.y, t0);
                    t0 = fmaf(a0 * a0, nisx, t0);
                    t0 = fmaf(b0 * b0, nisy, t0);
                    v0 = __expf(t0);
                    float a1 = pa1 + q0.x, b1 = pb1 + q0.y;
                    float t1 = negE1 - q0.z;
                    t1 = fmaf(gb0, q0.w, t1);
                    t1 = fmaf(gb1, q1.x, t1);
                    t1 = fmaf(gb2, q1.y, t1);
                    t1 = fmaf(a1 * a1, nisx, t1);
                    t1 = fmaf(b1 * b1, nisy, t1);
                    v1 = __expf(t1);
                }
                w[jp][0] = v0;
                w[jp][1] = v1;
            }
            den0 += w[0][0] + w[1][0] + w[2][0] + w[3][0];
            den1 += w[0][1] + w[1][1] + w[2][1] + w[3][1];

            uint32_t h0 = pack_bf16x2(w[0][0], w[1][0]);
            uint32_t h1 = pack_bf16x2(w[0][1], w[1][1]);
            uint32_t h2 = pack_bf16x2(w[2][0], w[3][0]);
            uint32_t h3 = pack_bf16x2(w[2][1], w[3][1]);
            ah[mt][ks][0] = h0; ah[mt][ks][1] = h1; ah[mt][ks][2] = h2; ah[mt][ks][3] = h3;
            al[mt][ks][0] = pack_bf16x2(w[0][0] - __uint_as_float(h0 << 16),
                                        w[1][0] - __uint_as_float(h0 & 0xffff0000u));
            al[mt][ks][1] = pack_bf16x2(w[0][1] - __uint_as_float(h1 << 16),
                                        w[1][1] - __uint_as_float(h1 & 0xffff0000u));
            al[mt][ks][2] = pack_bf16x2(w[2][0] - __uint_as_float(h2 << 16),
                                        w[3][0] - __uint_as_float(h2 & 0xffff0000u));
            al[mt][ks][3] = pack_bf16x2(w[2][1] - __uint_as_float(h3 << 16),
                                        w[3][1] - __uint_as_float(h3 & 0xffff0000u));
        }
        den0 += __shfl_xor_sync(0xffffffffu, den0, 1);
        den0 += __shfl_xor_sync(0xffffffffu, den0, 2);
        den1 += __shfl_xor_sync(0xffffffffu, den1, 1);
        den1 += __shfl_xor_sync(0xffffffffu, den1, 2);
        inv[mt][0] = 1.0f / fmaxf(den0, 1e-8f);
        inv[mt][1] = 1.0f / fmaxf(den1, 1e-8f);
    }

    __syncthreads();   // F4 ready

    // ---- phase 2b: stream channels; 1 LDS.128 feeds 6 MMAs ----
    const int ybase = uc * SCALE + zh * 8 + 2 * wid;
    float* ob0 = out + (size_t)ybase * WH + x0;          // mt 0
    float* ob1 = out + (size_t)(ybase + 1) * WH + x0;    // mt 1

#pragma unroll
    for (int ng = 0; ng < 8; ng++) {
#pragma unroll
        for (int h = 0; h < 2; h++) {
            const int cb = (2 * ng + h) * 8 + lq;
            float acc0[4] = {0.f, 0.f, 0.f, 0.f};
            float acc1[4] = {0.f, 0.f, 0.f, 0.f};
#pragma unroll
            for (int ks = 0; ks < 4; ks++) {
                if (ks >= ksteps) break;
                uint4 B = F4[(ks * 4 + lr) * CSTR4 + cb];
                MMA_BF16(acc0, ah[0][ks][0], ah[0][ks][1], ah[0][ks][2], ah[0][ks][3], B.x, B.y);
                MMA_BF16(acc0, al[0][ks][0], al[0][ks][1], al[0][ks][2], al[0][ks][3], B.x, B.y);
                MMA_BF16(acc0, ah[0][ks][0], ah[0][ks][1], ah[0][ks][2], ah[0][ks][3], B.z, B.w);
                MMA_BF16(acc1, ah[1][ks][0], ah[1][ks][1], ah[1][ks][2], ah[1][ks][3], B.x, B.y);
                MMA_BF16(acc1, al[1][ks][0], al[1][ks][1], al[1][ks][2], al[1][ks][3], B.x, B.y);
                MMA_BF16(acc1, ah[1][ks][0], ah[1][ks][1], ah[1][ks][2], ah[1][ks][3], B.z, B.w);
            }
            const int ch = (2 * ng + h) * 8 + lr * 2;
            float* o0 = ob0 + (size_t)ch * HW;
            float* o1 = ob1 + (size_t)ch * HW;
            o0[0]      = acc0[0] * inv[0][0];
            o0[HW]     = acc0[1] * inv[0][0];
            o0[8]      = acc0[2] * inv[0][1];
            o0[HW + 8] = acc0[3] * inv[0][1];
            o1[0]      = acc1[0] * inv[1][0];
            o1[HW]     = acc1[1] * inv[1][0];
            o1[8]      = acc1[2] * inv[1][1];
            o1[HW + 8] = acc1[3] * inv[1][1];
        }
    }
}

extern "C" void kernel_launch(void* const* d_in, const int* in_sizes, int n_in,
                              void* d_out, int out_size) {
    const float* feat  = (const float*)d_in[0];
    const float* guide = (const float*)d_in[1];
    const float* sx    = (const float*)d_in[2];
    const float* sy    = (const float*)d_in[3];
    const float* th    = (const float*)d_in[4];
    const float* sr    = (const float*)d_in[5];
    float* out = (float*)d_out;

    cudaFuncSetAttribute(jbu_main_kernel,
                         cudaFuncAttributeMaxDynamicSharedMemorySize, SMEM_BYTES);

    jbu_prep_kernel<<<512, 256>>>(feat, guide);
    dim3 grid(WL, HL, 2);
    jbu_main_kernel<<<grid, 128, SMEM_BYTES>>>(guide, sx, sy, th, sr, out);
}